// round 1
// baseline (speedup 1.0000x reference)
#include <cuda_runtime.h>
#include <math.h>

// Problem constants (fixed by reference)
#define BB 4
#define NN 20000
#define SS 2048
#define CC 64
#define DD 64
#define INV_T (1.0f / 0.7f)

#define TM 64
#define TN 64
#define ROWTILES (SS / TM)   // 32 per batch

// Scratch (no allocations allowed -> device globals)
__device__ int   g_inv_perm[BB * NN];
__device__ float g_Vn[(size_t)BB * CC * SS];   // [b][k][s]  k-major normalized vehicle feats
__device__ float g_Fn[(size_t)BB * CC * SS];   // [b][k][s]  k-major normalized fusion feats
__device__ float g_partials[BB * ROWTILES];    // per-block partial loss (already /S)

// ---------------------------------------------------------------------------
// Kernel 0: inverse permutation. inv[shuf[i]] = i  (argsort of a permutation)
// ---------------------------------------------------------------------------
__global__ void k_scatter_inv(const int* __restrict__ shuf) {
    int i = blockIdx.x * blockDim.x + threadIdx.x;
    if (i < BB * NN) {
        int b = i / NN;
        int local = i - b * NN;
        int v = shuf[i];
        g_inv_perm[b * NN + v] = local;
    }
}

// ---------------------------------------------------------------------------
// Kernel 1: gather voxel features for sampled points, L2-normalize, store
// k-major into g_Vn / g_Fn. One warp per (b, s) row.
// ---------------------------------------------------------------------------
__global__ void k_gather_norm(const float* __restrict__ dv,
                              const int*   __restrict__ vcoor,
                              const float* __restrict__ df,
                              const int*   __restrict__ fcoor,
                              const int*   __restrict__ samp_idx) {
    int w    = (blockIdx.x * blockDim.x + threadIdx.x) >> 5;
    int lane = threadIdx.x & 31;
    if (w >= BB * SS) return;
    int b = w / SS;
    int s = w - b * SS;

    int samp = samp_idx[b * SS + s];

    // vehicle
    {
        const int* cp = vcoor + ((size_t)b * NN + samp) * 3;
        int c0 = cp[0] >> 3, c1 = cp[1] >> 3, c2 = cp[2] >> 3;
        const float* src = dv + ((((size_t)b * DD + c0) * DD + c1) * DD + c2) * (size_t)CC;
        float v0 = src[lane];
        float v1 = src[lane + 32];
        float ss = v0 * v0 + v1 * v1;
        #pragma unroll
        for (int o = 16; o; o >>= 1) ss += __shfl_xor_sync(0xffffffffu, ss, o);
        float inv = 1.0f / fmaxf(sqrtf(ss), 1e-12f);
        g_Vn[((size_t)b * CC + lane)      * SS + s] = v0 * inv;
        g_Vn[((size_t)b * CC + lane + 32) * SS + s] = v1 * inv;
    }
    // fusion (through inverse permutation)
    {
        int fid = g_inv_perm[b * NN + samp];
        const int* cp = fcoor + ((size_t)b * NN + fid) * 3;
        int c0 = cp[0] >> 3, c1 = cp[1] >> 3, c2 = cp[2] >> 3;
        const float* src = df + ((((size_t)b * DD + c0) * DD + c1) * DD + c2) * (size_t)CC;
        float v0 = src[lane];
        float v1 = src[lane + 32];
        float ss = v0 * v0 + v1 * v1;
        #pragma unroll
        for (int o = 16; o; o >>= 1) ss += __shfl_xor_sync(0xffffffffu, ss, o);
        float inv = 1.0f / fmaxf(sqrtf(ss), 1e-12f);
        g_Fn[((size_t)b * CC + lane)      * SS + s] = v0 * inv;
        g_Fn[((size_t)b * CC + lane + 32) * SS + s] = v1 * inv;
    }
}

// ---------------------------------------------------------------------------
// Kernel 2: per-64-row-tile GEMM (S x S x 64) + exp + row-sum + diag, fused.
// Block = 256 threads, 4x4 register micro-tile, smem tiles are k-major.
// Deterministic per-block partial written to g_partials.
// ---------------------------------------------------------------------------
__global__ __launch_bounds__(256) void k_loss() {
    __shared__ float Vt[CC][TM + 4];  // [k][row], stride 68 floats (16B aligned: 272B)
    __shared__ float Ft[CC][TN + 4];  // [k][col]
    __shared__ float s_rowsum[TM];
    __shared__ float s_diag[TM];
    __shared__ float s_loss[TM];

    int rt = blockIdx.x;              // 0 .. B*32-1
    int b = rt >> 5;
    int rowbase = (rt & 31) * TM;

    int t  = threadIdx.x;
    int tr = t >> 4;                  // 0..15 -> rows tr*4 .. tr*4+3
    int tc = t & 15;                  // 0..15 -> cols tc*4 .. tc*4+3

    const float* Vbase = g_Vn + (size_t)b * CC * SS;
    const float* Fbase = g_Fn + (size_t)b * CC * SS;

    // Load V tile (64 k x 64 rows) once. 1024 float4 / 256 threads = 4 each.
    #pragma unroll
    for (int q = 0; q < 4; q++) {
        int idx = q * 256 + t;
        int k   = idx >> 4;
        int seg = idx & 15;
        float4 v = *(const float4*)(Vbase + (size_t)k * SS + rowbase + seg * 4);
        *(float4*)&Vt[k][seg * 4] = v;
    }

    float rowsum[4] = {0.f, 0.f, 0.f, 0.f};

    for (int ct = 0; ct < SS / TN; ++ct) {
        __syncthreads();   // previous tile's compute done before overwrite
        #pragma unroll
        for (int q = 0; q < 4; q++) {
            int idx = q * 256 + t;
            int k   = idx >> 4;
            int seg = idx & 15;
            float4 v = *(const float4*)(Fbase + (size_t)k * SS + ct * TN + seg * 4);
            *(float4*)&Ft[k][seg * 4] = v;
        }
        __syncthreads();

        float acc[4][4];
        #pragma unroll
        for (int i = 0; i < 4; i++)
            #pragma unroll
            for (int j = 0; j < 4; j++) acc[i][j] = 0.f;

        #pragma unroll 8
        for (int k = 0; k < CC; k++) {
            float4 va = *(const float4*)&Vt[k][tr * 4];
            float4 fb = *(const float4*)&Ft[k][tc * 4];
            acc[0][0] += va.x * fb.x; acc[0][1] += va.x * fb.y;
            acc[0][2] += va.x * fb.z; acc[0][3] += va.x * fb.w;
            acc[1][0] += va.y * fb.x; acc[1][1] += va.y * fb.y;
            acc[1][2] += va.y * fb.z; acc[1][3] += va.y * fb.w;
            acc[2][0] += va.z * fb.x; acc[2][1] += va.z * fb.y;
            acc[2][2] += va.z * fb.z; acc[2][3] += va.z * fb.w;
            acc[3][0] += va.w * fb.x; acc[3][1] += va.w * fb.y;
            acc[3][2] += va.w * fb.z; acc[3][3] += va.w * fb.w;
        }

        #pragma unroll
        for (int i = 0; i < 4; i++) {
            int r = rowbase + tr * 4 + i;          // global row
            #pragma unroll
            for (int j = 0; j < 4; j++) {
                int c = ct * TN + tc * 4 + j;      // global col
                float sv = acc[i][j];
                if (c == r) s_diag[tr * 4 + i] = sv;   // unique writer
                rowsum[i] += __expf(sv * INV_T);
            }
        }
    }

    // Reduce rowsum across the 16 tc-threads of each row group (contiguous
    // 16-lane segments of a warp).
    #pragma unroll
    for (int i = 0; i < 4; i++) {
        float v = rowsum[i];
        #pragma unroll
        for (int o = 8; o; o >>= 1) v += __shfl_down_sync(0xffffffffu, v, o, 16);
        if (tc == 0) s_rowsum[tr * 4 + i] = v;
    }
    __syncthreads();

    if (t < TM) {
        s_loss[t] = logf(s_rowsum[t]) - s_diag[t] * INV_T;
    }
    __syncthreads();

    if (t == 0) {
        float tot = 0.f;
        #pragma unroll
        for (int i = 0; i < TM; i++) tot += s_loss[i];
        g_partials[rt] = tot * (1.0f / (float)SS);
    }
}

// ---------------------------------------------------------------------------
// Kernel 3: deterministic fixed-order final reduction of 128 partials.
// ---------------------------------------------------------------------------
__global__ void k_final(float* __restrict__ out) {
    if (threadIdx.x == 0) {
        float tot = 0.f;
        for (int i = 0; i < BB * ROWTILES; i++) tot += g_partials[i];
        out[0] = tot;
    }
}

// ---------------------------------------------------------------------------
extern "C" void kernel_launch(void* const* d_in, const int* in_sizes, int n_in,
                              void* d_out, int out_size) {
    const float* dv    = (const float*)d_in[0];  // dense_vehicle_voxel_feats (B,D,H,W,C)
    const int*   vcoor = (const int*)  d_in[1];  // vehicle_voxels_coors (B,N,3)
    const float* df    = (const float*)d_in[2];  // dense_fusion_voxel_feats
    const int*   fcoor = (const int*)  d_in[3];  // fusion_voxels_coors
    const int*   shuf  = (const int*)  d_in[4];  // fusion_points_shuffled_idx (B,N)
    // d_in[5] = vehicle_points (unused by reference)
    const int*   samp  = (const int*)  d_in[6];  // sampled_idx (B,S)

    k_scatter_inv<<<(BB * NN + 255) / 256, 256>>>(shuf);
    k_gather_norm<<<(BB * SS * 32 + 255) / 256, 256>>>(dv, vcoor, df, fcoor, samp);
    k_loss<<<BB * ROWTILES, 256>>>();
    k_final<<<1, 32>>>((float*)d_out);
}

// round 4
// speedup vs baseline: 6.6099x; 6.6099x over previous
#include <cuda_runtime.h>
#include <cuda_bf16.h>
#include <cstdint>
#include <math.h>

// ---------------------------------------------------------------- constants
#define BB 4
#define NN 20000
#define SS 2048
#define CC 64
#define DD 64
#define INV_T 1.4285714285714286f

#define TILE_M 64
#define TN 128
#define NCH (SS / TN)          // 16 column chunks
#define TPB (SS / TILE_M)      // 32 row tiles per batch
#define NCTA (BB * TPB)        // 128 CTAs

// ---------------------------------------------------------------- scratch
__device__ __align__(256) __nv_bfloat16 g_Vn[(size_t)BB * SS * CC];
__device__ __align__(256) __nv_bfloat16 g_Fn[(size_t)BB * SS * CC];
__device__ int   g_inv_perm[BB * NN];
__device__ float g_partials[NCTA];
__device__ int   g_count;   // zero-init; reset by last CTA each run

// ---------------------------------------------------------------- helpers
__device__ __forceinline__ uint32_t smem_u32(const void* p) {
    uint32_t a;
    asm("{ .reg .u64 t; cvta.to.shared.u64 t, %1; cvt.u32.u64 %0, t; }" : "=r"(a) : "l"(p));
    return a;
}

__device__ __forceinline__ void cpa16(uint32_t dst, const void* src) {
    asm volatile("cp.async.cg.shared.global [%0], [%1], 16;" :: "r"(dst), "l"(src));
}
#define CP_COMMIT() asm volatile("cp.async.commit_group;" ::: "memory")
#define CP_WAIT(n)  asm volatile("cp.async.wait_group %0;" :: "n"(n) : "memory")

#define LDSM4(r0, r1, r2, r3, addr)                                            \
    asm volatile("ldmatrix.sync.aligned.m8n8.x4.shared.b16 {%0,%1,%2,%3}, [%4];" \
                 : "=r"(r0), "=r"(r1), "=r"(r2), "=r"(r3) : "r"(addr))

__device__ __forceinline__ void mma16816(float* c, const uint32_t* a,
                                         uint32_t b0, uint32_t b1) {
    asm volatile(
        "mma.sync.aligned.m16n8k16.row.col.f32.bf16.bf16.f32 "
        "{%0,%1,%2,%3}, {%4,%5,%6,%7}, {%8,%9}, {%0,%1,%2,%3};"
        : "+f"(c[0]), "+f"(c[1]), "+f"(c[2]), "+f"(c[3])
        : "r"(a[0]), "r"(a[1]), "r"(a[2]), "r"(a[3]), "r"(b0), "r"(b1));
}

// ---------------------------------------------------------------- kernel 0
__global__ void k_scatter_inv(const int* __restrict__ shuf) {
    int i = blockIdx.x * blockDim.x + threadIdx.x;
    if (i < BB * NN) {
        int b = i / NN;
        int local = i - b * NN;
        g_inv_perm[b * NN + shuf[i]] = local;
    }
}

// ---------------------------------------------------------------- kernel 1
// gather voxel features, L2-normalize in fp32, store bf16 row-major [b][s][k]
__global__ void k_gather_norm(const float* __restrict__ dv,
                              const int*   __restrict__ vcoor,
                              const float* __restrict__ df,
                              const int*   __restrict__ fcoor,
                              const int*   __restrict__ samp_idx) {
    int w    = (blockIdx.x * blockDim.x + threadIdx.x) >> 5;
    int lane = threadIdx.x & 31;
    if (w >= BB * SS) return;
    int b = w / SS;
    int s = w - b * SS;

    int samp = samp_idx[b * SS + s];
    size_t rowbase = ((size_t)b * SS + s) * CC;

    {   // vehicle
        const int* cp = vcoor + ((size_t)b * NN + samp) * 3;
        int c0 = cp[0] >> 3, c1 = cp[1] >> 3, c2 = cp[2] >> 3;
        const float* src = dv + ((((size_t)b * DD + c0) * DD + c1) * DD + c2) * (size_t)CC;
        float v0 = src[lane], v1 = src[lane + 32];
        float ssq = v0 * v0 + v1 * v1;
        #pragma unroll
        for (int o = 16; o; o >>= 1) ssq += __shfl_xor_sync(0xffffffffu, ssq, o);
        float inv = 1.0f / fmaxf(sqrtf(ssq), 1e-12f);
        g_Vn[rowbase + lane]      = __float2bfloat16(v0 * inv);
        g_Vn[rowbase + lane + 32] = __float2bfloat16(v1 * inv);
    }
    {   // fusion (through inverse permutation)
        int fid = g_inv_perm[b * NN + samp];
        const int* cp = fcoor + ((size_t)b * NN + fid) * 3;
        int c0 = cp[0] >> 3, c1 = cp[1] >> 3, c2 = cp[2] >> 3;
        const float* src = df + ((((size_t)b * DD + c0) * DD + c1) * DD + c2) * (size_t)CC;
        float v0 = src[lane], v1 = src[lane + 32];
        float ssq = v0 * v0 + v1 * v1;
        #pragma unroll
        for (int o = 16; o; o >>= 1) ssq += __shfl_xor_sync(0xffffffffu, ssq, o);
        float inv = 1.0f / fmaxf(sqrtf(ssq), 1e-12f);
        g_Fn[rowbase + lane]      = __float2bfloat16(v0 * inv);
        g_Fn[rowbase + lane + 32] = __float2bfloat16(v1 * inv);
    }
}

// ---------------------------------------------------------------- kernel 2
// Fused bf16 mma.sync GEMM (64 x 2048 x 64 per CTA) + exp/rowsum/diag + loss.
// 8 warps: warps 0-3 cols [0,64) of each chunk, warps 4-7 cols [64,128).
// Rows: warp (w&3) owns rows (w&3)*16 .. +15.  Registers hold accumulators.
__global__ __launch_bounds__(256, 1) void k_loss(float* __restrict__ out) {
    __shared__ __align__(128) unsigned char sA[TILE_M * 128];      // 8 KB
    __shared__ __align__(128) unsigned char sB[2][TN * 128];       // 32 KB
    __shared__ float ssum[2][TILE_M];
    __shared__ float sdiag[TILE_M];
    __shared__ float sloss[TILE_M];

    const int tid = threadIdx.x;
    const int w   = tid >> 5;
    const int l   = tid & 31;
    const int cta = blockIdx.x;
    const int b      = cta >> 5;
    const int mytile = cta & 31;
    const int g  = w >> 2;          // column half group
    const int wr = (w & 3) * 16;    // warp row base (local)

    const __nv_bfloat16* Ag = g_Vn + ((size_t)b * SS + (size_t)mytile * TILE_M) * CC;
    const __nv_bfloat16* Fg = g_Fn + (size_t)b * SS * CC;

    const uint32_t sAu  = smem_u32(sA);
    const uint32_t sBu0 = smem_u32(sB[0]);
    const uint32_t sBu1 = smem_u32(sB[1]);

    // ---- prologue: group0 = A + B0, group1 = B1
    for (int i = tid; i < 512; i += 256) {
        int r = i >> 3, c = i & 7;
        cpa16(sAu + r * 128 + ((c ^ (r & 7)) << 4), (const char*)Ag + r * 128 + c * 16);
    }
    for (int i = tid; i < 1024; i += 256) {
        int r = i >> 3, c = i & 7;
        cpa16(sBu0 + r * 128 + ((c ^ (r & 7)) << 4), (const char*)Fg + r * 128 + c * 16);
    }
    CP_COMMIT();
    for (int i = tid; i < 1024; i += 256) {
        int r = i >> 3, c = i & 7;
        cpa16(sBu1 + r * 128 + ((c ^ (r & 7)) << 4),
              (const char*)Fg + (size_t)TN * 128 + r * 128 + c * 16);
    }
    CP_COMMIT();
    CP_WAIT(1);
    __syncthreads();

    // ---- A fragments (constant across all chunks): 4 k-steps x 4 regs
    uint32_t afr[4][4];
    {
        int row = wr + (l & 15);
        #pragma unroll
        for (int kk = 0; kk < 4; kk++) {
            int kb = kk * 32 + (l >> 4) * 16;
            uint32_t ad = sAu + row * 128 + (((kb >> 4) ^ (row & 7)) << 4);
            LDSM4(afr[kk][0], afr[kk][1], afr[kk][2], afr[kk][3], ad);
        }
    }

    const int r0 = wr + (l >> 2), r1 = r0 + 8;      // local rows (0..63)
    const bool mygrp = (g == (mytile & 1));
    const int dct = mytile >> 1;                    // chunk containing diagonal
    float rs0 = 0.f, rs1 = 0.f, d0 = 0.f, d1 = 0.f;

    // per-lane B address components (constant)
    const int nlane = (l & 7) + ((l >> 4) << 3);
    const int kblane = ((l >> 3) & 1) * 16;

    for (int ct = 0; ct < NCH; ++ct) {
        const uint32_t sBu = (ct & 1) ? sBu1 : sBu0;
        const bool dg = mygrp && (ct == dct);

        #pragma unroll
        for (int jp = 0; jp < 4; ++jp) {
            float a0[4] = {0.f, 0.f, 0.f, 0.f};
            float a1[4] = {0.f, 0.f, 0.f, 0.f};
            #pragma unroll
            for (int kk = 0; kk < 4; ++kk) {
                int n  = g * 64 + jp * 16 + nlane;
                int kb = kk * 32 + kblane;
                uint32_t ad = sBu + n * 128 + (((kb >> 4) ^ (n & 7)) << 4);
                uint32_t b0, b1, b2, b3;
                LDSM4(b0, b1, b2, b3, ad);
                mma16816(a0, afr[kk], b0, b1);
                mma16816(a1, afr[kk], b2, b3);
            }
            int c00 = jp * 16 + (l & 3) * 2;   // col offset within this 64-half
            int c10 = c00 + 8;
            if (dg) {
                if (c00     == r0) d0 = a0[0];
                if (c00 + 1 == r0) d0 = a0[1];
                if (c10     == r0) d0 = a1[0];
                if (c10 + 1 == r0) d0 = a1[1];
                if (c00     == r1) d1 = a0[2];
                if (c00 + 1 == r1) d1 = a0[3];
                if (c10     == r1) d1 = a1[2];
                if (c10 + 1 == r1) d1 = a1[3];
            }
            rs0 += __expf(a0[0] * INV_T) + __expf(a0[1] * INV_T)
                 + __expf(a1[0] * INV_T) + __expf(a1[1] * INV_T);
            rs1 += __expf(a0[2] * INV_T) + __expf(a0[3] * INV_T)
                 + __expf(a1[2] * INV_T) + __expf(a1[3] * INV_T);
        }

        __syncthreads();   // all warps done reading this buffer
        if (ct + 2 < NCH) {
            uint32_t dstB = (ct & 1) ? sBu1 : sBu0;
            const char* src = (const char*)Fg + (size_t)(ct + 2) * TN * 128;
            for (int i = tid; i < 1024; i += 256) {
                int r = i >> 3, c = i & 7;
                cpa16(dstB + r * 128 + ((c ^ (r & 7)) << 4), src + r * 128 + c * 16);
            }
            CP_COMMIT();
            CP_WAIT(1);        // B(ct+1) complete, B(ct+2) may be in flight
            __syncthreads();
        } else if (ct + 1 < NCH) {
            CP_WAIT(0);        // last buffer must be fully landed
            __syncthreads();
        }
    }

    // ---- reduce within quads (lanes sharing l>>2 hold same rows)
    #pragma unroll
    for (int o = 1; o <= 2; o <<= 1) {
        rs0 += __shfl_xor_sync(0xffffffffu, rs0, o);
        rs1 += __shfl_xor_sync(0xffffffffu, rs1, o);
        d0  += __shfl_xor_sync(0xffffffffu, d0, o);
        d1  += __shfl_xor_sync(0xffffffffu, d1, o);
    }
    if ((l & 3) == 0) {
        ssum[g][r0] = rs0;
        ssum[g][r1] = rs1;
        if (mygrp) { sdiag[r0] = d0; sdiag[r1] = d1; }
    }
    __syncthreads();

    if (tid < TILE_M) {
        float tot = ssum[0][tid] + ssum[1][tid];
        sloss[tid] = logf(tot) - sdiag[tid] * INV_T;
    }
    __syncthreads();

    if (tid == 0) {
        float part = 0.f;
        #pragma unroll
        for (int i = 0; i < TILE_M; ++i) part += sloss[i];
        g_partials[cta] = part * (1.0f / (float)SS);
        __threadfence();
        int n = atomicAdd(&g_count, 1);
        if (n == NCTA - 1) {
            __threadfence();
            const volatile float* gp = (const volatile float*)g_partials;
            float tot = 0.f;
            for (int i = 0; i < NCTA; ++i) tot += gp[i];
            out[0] = tot;
            g_count = 0;   // reset for next graph replay
        }
    }
}

// ---------------------------------------------------------------- launch
extern "C" void kernel_launch(void* const* d_in, const int* in_sizes, int n_in,
                              void* d_out, int out_size) {
    const float* dv    = (const float*)d_in[0];
    const int*   vcoor = (const int*)  d_in[1];
    const float* df    = (const float*)d_in[2];
    const int*   fcoor = (const int*)  d_in[3];
    const int*   shuf  = (const int*)  d_in[4];
    // d_in[5] = vehicle_points (unused)
    const int*   samp  = (const int*)  d_in[6];

    k_scatter_inv<<<(BB * NN + 255) / 256, 256>>>(shuf);
    k_gather_norm<<<(BB * SS * 32 + 255) / 256, 256>>>(dv, vcoor, df, fcoor, samp);
    k_loss<<<NCTA, 256>>>((float*)d_out);
}